// round 2
// baseline (speedup 1.0000x reference)
#include <cuda_runtime.h>
#include <math.h>

#define HH   1024
#define NH   32
#define LLEN 4096

__device__ __forceinline__ unsigned long long ffma2(
    unsigned long long a, unsigned long long b, unsigned long long c)
{
    unsigned long long d;
    asm("fma.rn.f32x2 %0, %1, %2, %3;" : "=l"(d) : "l"(a), "l"(b), "l"(c));
    return d;
}

union F4U2 { float4 f; unsigned long long u[2]; };

__global__ __launch_bounds__(128, 4) void s4d_kernel(
    const float* __restrict__ log_dt,
    const float* __restrict__ C_real,
    const float* __restrict__ log_A_real,
    const float* __restrict__ A_imag,
    float* __restrict__ out)
{
    // 48 KB exactly: anchors for the per-h 64x64x32 complex->real contraction
    __shared__ __align__(16) float  Pr [NH][64];   // 2*Cd * z^a        (real)
    __shared__ __align__(16) float  Pim[NH][64];   // -(2*Cd * z^a)     (imag, negated)
    __shared__ __align__(16) float2 Qrd[NH][64];   // {q,q} dup, q = Re z^(64b)
    __shared__ __align__(16) float2 Qid[NH][64];   // {q,q} dup, q = Im z^(64b)

    const int h   = blockIdx.x;
    const int tid = threadIdx.x;

    // ================= precompute: each thread owns one n, 32 anchors =========
    {
        const int n    = tid >> 2;     // 0..31
        const int part = tid & 3;      // 0,1 -> P anchors; 2,3 -> Q anchors

        const float dt  = expf(log_dt[h]);
        const float Arf = -expf(log_A_real[h * NH + n]);
        const float Aif = A_imag[h * NH + n];
        const float dtArf = dt * Arf;        // matches reference f32 product
        const float dtAif = dt * Aif;

        // Cd = C * (exp(dtA)-1)/A  in double (f32 cancels badly at small dt)
        const double er = exp((double)dtArf);
        double sy, cy;
        sincos((double)dtAif, &sy, &cy);
        const double numr = er * cy - 1.0;
        const double numi = er * sy;
        const double den  = (double)Arf * (double)Arf + (double)Aif * (double)Aif;
        const double tr = (numr * (double)Arf + numi * (double)Aif) / den;
        const double ti = (numi * (double)Arf - numr * (double)Aif) / den;
        const float Cr = C_real[(h * NH + n) * 2 + 0];
        const float Ci = C_real[(h * NH + n) * 2 + 1];
        const float cdr2 = (float)(2.0 * ((double)Cr * tr - (double)Ci * ti));
        const float cdi2 = (float)(2.0 * ((double)Cr * ti + (double)Ci * tr));

        const double dtAi_d = (double)dtAif;
        const double INV2PI = 0.15915494309189534561;
        const double TWOPI  = 6.28318530717958647693;

        if (part < 2) {
            const int a0 = part * 32;
            #pragma unroll 4
            for (int j = 0; j < 32; j++) {
                const int a = a0 + j;
                const double ph = dtAi_d * (double)a;
                const double kk = rint(ph * INV2PI);
                const float red = (float)fma(-kk, TWOPI, ph);  // |red|<=pi, ~1e-12 exact
                float sf, cf;
                __sincosf(red, &sf, &cf);
                const float ef = __expf(dtArf * (float)a);
                const float wr = ef * cf, wi = ef * sf;
                Pr [n][a] = cdr2 * wr - cdi2 * wi;
                Pim[n][a] = -(cdr2 * wi + cdi2 * wr);
            }
        } else {
            const int b0 = (part - 2) * 32;
            #pragma unroll 4
            for (int j = 0; j < 32; j++) {
                const int b = b0 + j;
                const double lv = (double)(64 * b);
                const double ph = dtAi_d * lv;
                const double kk = rint(ph * INV2PI);
                const float red = (float)fma(-kk, TWOPI, ph);
                float sf, cf;
                __sincosf(red, &sf, &cf);
                const float ef = __expf(dtArf * (float)(64 * b));
                const float wr = ef * cf, wi = ef * sf;
                Qrd[n][b] = make_float2(wr, wr);
                Qid[n][b] = make_float2(wi, wi);
            }
        }
    }
    __syncthreads();

    // ================= main loop: 8a x 4b per thread, packed f32x2 FMA ========
    const int tx = tid & 7;          // a-tile
    const int ty = tid >> 3;         // b-tile
    const int a0 = tx * 8;
    const int b0 = ty * 4;

    unsigned long long acc[4][4];    // [b][a-pack], each pack = 2 floats
    #pragma unroll
    for (int jb = 0; jb < 4; jb++)
        #pragma unroll
        for (int ia = 0; ia < 4; ia++) acc[jb][ia] = 0ULL;

    #pragma unroll 16
    for (int n = 0; n < NH; n++) {
        F4U2 p0, p1, m0, m1, qr01, qr23, qi01, qi23;
        p0.f   = *(const float4*)&Pr [n][a0];
        p1.f   = *(const float4*)&Pr [n][a0 + 4];
        m0.f   = *(const float4*)&Pim[n][a0];
        m1.f   = *(const float4*)&Pim[n][a0 + 4];
        qr01.f = *(const float4*)&Qrd[n][b0];      // {qr(b0)dup, qr(b0+1)dup}
        qr23.f = *(const float4*)&Qrd[n][b0 + 2];
        qi01.f = *(const float4*)&Qid[n][b0];
        qi23.f = *(const float4*)&Qid[n][b0 + 2];

        const unsigned long long pp[4] = { p0.u[0], p0.u[1], p1.u[0], p1.u[1] };
        const unsigned long long mm[4] = { m0.u[0], m0.u[1], m1.u[0], m1.u[1] };
        const unsigned long long qrb[4] = { qr01.u[0], qr01.u[1], qr23.u[0], qr23.u[1] };
        const unsigned long long qib[4] = { qi01.u[0], qi01.u[1], qi23.u[0], qi23.u[1] };

        #pragma unroll
        for (int jb = 0; jb < 4; jb++) {
            #pragma unroll
            for (int ia = 0; ia < 4; ia++) {
                acc[jb][ia] = ffma2(pp[ia], qrb[jb], acc[jb][ia]);
                acc[jb][ia] = ffma2(mm[ia], qib[jb], acc[jb][ia]);
            }
        }
    }

    // ================= store: K[h][ (b0+jb)*64 + a0 .. +7 ] ===================
    float* outh = out + (size_t)h * LLEN;
    #pragma unroll
    for (int jb = 0; jb < 4; jb++) {
        F4U2 lo, hi;
        lo.u[0] = acc[jb][0]; lo.u[1] = acc[jb][1];
        hi.u[0] = acc[jb][2]; hi.u[1] = acc[jb][3];
        float* dst = &outh[(b0 + jb) * 64 + a0];
        *(float4*)(dst)     = lo.f;
        *(float4*)(dst + 4) = hi.f;
    }
}

extern "C" void kernel_launch(void* const* d_in, const int* in_sizes, int n_in,
                              void* d_out, int out_size)
{
    const float* log_dt     = (const float*)d_in[0];
    const float* C_real     = (const float*)d_in[1];
    const float* log_A_real = (const float*)d_in[2];
    const float* A_imag     = (const float*)d_in[3];
    float* out = (float*)d_out;
    s4d_kernel<<<HH, 128>>>(log_dt, C_real, log_A_real, A_imag, out);
}

// round 5
// speedup vs baseline: 1.4153x; 1.4153x over previous
#include <cuda_runtime.h>
#include <math.h>

#define HH   1024
#define NH   32
#define LLEN 4096

__device__ __forceinline__ unsigned long long ffma2(
    unsigned long long a, unsigned long long b, unsigned long long c)
{
    unsigned long long d;
    asm("fma.rn.f32x2 %0, %1, %2, %3;" : "=l"(d) : "l"(a), "l"(b), "l"(c));
    return d;
}

union F4U2 { float4 f; unsigned long long u[2]; };

// Dynamic shared memory layout (50176 bytes total)
struct SmemLayout {
    float  Pr [NH][64];    //  8 KB : 2*Cd * z^a        (real)
    float  Pim[NH][64];    //  8 KB : -(2*Cd * z^a)     (imag, negated)
    float2 Qrd[NH][64];    // 16 KB : {q,q} dup, q = Re z^(64b)
    float2 Qid[NH][64];    // 16 KB : {q,q} dup, q = Im z^(64b)
    double sdtAr[NH];      //  1 KB scalars below
    double sdtAi[NH];
    double sCdr[NH];
    double sCdi[NH];
};

__global__ __launch_bounds__(256, 4) void s4d_kernel(
    const float* __restrict__ log_dt,
    const float* __restrict__ C_real,
    const float* __restrict__ log_A_real,
    const float* __restrict__ A_imag,
    float* __restrict__ out)
{
    extern __shared__ __align__(16) char smem_raw[];
    SmemLayout& S = *reinterpret_cast<SmemLayout*>(smem_raw);

    const int h   = blockIdx.x;
    const int tid = threadIdx.x;

    // ---- phase 1: per-(h,n) scalars in double (32 threads only) --------------
    if (tid < NH) {
        const int n = tid;
        const float dt  = expf(log_dt[h]);
        const float Arf = -expf(log_A_real[h * NH + n]);
        const float Aif = A_imag[h * NH + n];
        const float dtArf = dt * Arf;        // matches reference f32 product
        const float dtAif = dt * Aif;
        const double er = exp((double)dtArf);
        double sy, cy;
        sincos((double)dtAif, &sy, &cy);
        const double numr = er * cy - 1.0;
        const double numi = er * sy;
        const double den  = (double)Arf * (double)Arf + (double)Aif * (double)Aif;
        const double tr = (numr * (double)Arf + numi * (double)Aif) / den;
        const double ti = (numi * (double)Arf - numr * (double)Aif) / den;
        const float Cr = C_real[(h * NH + n) * 2 + 0];
        const float Ci = C_real[(h * NH + n) * 2 + 1];
        S.sCdr[n] = 2.0 * ((double)Cr * tr - (double)Ci * ti);   // fold the 2x here
        S.sCdi[n] = 2.0 * ((double)Cr * ti + (double)Ci * tr);
        S.sdtAr[n] = (double)dtArf;
        S.sdtAi[n] = (double)dtAif;
    }
    __syncthreads();

    // ---- phase 2: anchors, 16 per thread -------------------------------------
    {
        const double INV2PI = 0.15915494309189534561;
        const double TWOPI  = 6.28318530717958647693;
        #pragma unroll
        for (int e = tid; e < NH * 128; e += 256) {
            const int n   = e >> 7;
            const int idx = e & 127;
            const double lv = (idx < 64) ? (double)idx : (double)((idx - 64) * 64);
            const double mr = S.sdtAr[n] * lv;
            const double ph = S.sdtAi[n] * lv;
            const double kk = rint(ph * INV2PI);
            const float red = (float)fma(-kk, TWOPI, ph);  // |red|<=pi, ~1e-12 exact
            float sf, cf;
            __sincosf(red, &sf, &cf);
            const float ef = __expf((float)mr);
            const float wr = ef * cf;
            const float wi = ef * sf;
            if (idx < 64) {
                const float cdr = (float)S.sCdr[n], cdi = (float)S.sCdi[n];
                S.Pr [n][idx] = cdr * wr - cdi * wi;
                S.Pim[n][idx] = -(cdr * wi + cdi * wr);
            } else {
                const int b = idx - 64;
                S.Qrd[n][b] = make_float2(wr, wr);
                S.Qid[n][b] = make_float2(wi, wi);
            }
        }
    }
    __syncthreads();

    // ---- main loop: 4a x 4b per thread, packed f32x2 FMA ---------------------
    const int tx = tid & 15;     // a tile (fast output dim -> coalesced stores)
    const int ty = tid >> 4;     // b tile
    const int a0 = tx * 4;
    const int b0 = ty * 4;

    unsigned long long acc[4][2];   // [b][a-pack]
    #pragma unroll
    for (int jb = 0; jb < 4; jb++) { acc[jb][0] = 0ULL; acc[jb][1] = 0ULL; }

    #pragma unroll 8
    for (int n = 0; n < NH; n++) {
        F4U2 p, m, qr01, qr23, qi01, qi23;
        p.f    = *(const float4*)&S.Pr [n][a0];    // 2 packs along a
        m.f    = *(const float4*)&S.Pim[n][a0];
        qr01.f = *(const float4*)&S.Qrd[n][b0];    // {qr(b0)dup, qr(b0+1)dup}
        qr23.f = *(const float4*)&S.Qrd[n][b0 + 2];
        qi01.f = *(const float4*)&S.Qid[n][b0];
        qi23.f = *(const float4*)&S.Qid[n][b0 + 2];

        const unsigned long long qrb[4] = { qr01.u[0], qr01.u[1], qr23.u[0], qr23.u[1] };
        const unsigned long long qib[4] = { qi01.u[0], qi01.u[1], qi23.u[0], qi23.u[1] };

        #pragma unroll
        for (int jb = 0; jb < 4; jb++) {
            acc[jb][0] = ffma2(p.u[0], qrb[jb], acc[jb][0]);
            acc[jb][1] = ffma2(p.u[1], qrb[jb], acc[jb][1]);
            acc[jb][0] = ffma2(m.u[0], qib[jb], acc[jb][0]);
            acc[jb][1] = ffma2(m.u[1], qib[jb], acc[jb][1]);
        }
    }

    // ---- store: K[h][(b0+jb)*64 + a0 .. a0+3] --------------------------------
    float* outh = out + (size_t)h * LLEN;
    #pragma unroll
    for (int jb = 0; jb < 4; jb++) {
        F4U2 v;
        v.u[0] = acc[jb][0];
        v.u[1] = acc[jb][1];
        *(float4*)&outh[(b0 + jb) * 64 + a0] = v.f;
    }
}

extern "C" void kernel_launch(void* const* d_in, const int* in_sizes, int n_in,
                              void* d_out, int out_size)
{
    const float* log_dt     = (const float*)d_in[0];
    const float* C_real     = (const float*)d_in[1];
    const float* log_A_real = (const float*)d_in[2];
    const float* A_imag     = (const float*)d_in[3];
    float* out = (float*)d_out;

    const int smem_bytes = (int)sizeof(SmemLayout);   // 50176
    cudaFuncSetAttribute(s4d_kernel,
                         cudaFuncAttributeMaxDynamicSharedMemorySize, smem_bytes);
    s4d_kernel<<<HH, 256, smem_bytes>>>(log_dt, C_real, log_A_real, A_imag, out);
}

// round 6
// speedup vs baseline: 1.5885x; 1.1224x over previous
#include <cuda_runtime.h>
#include <math.h>

#define HH   1024
#define NH   32
#define LLEN 4096

__global__ __launch_bounds__(256, 5) void s4d_kernel(
    const float* __restrict__ log_dt,
    const float* __restrict__ C_real,
    const float* __restrict__ log_A_real,
    const float* __restrict__ A_imag,
    float* __restrict__ out)
{
    // 33.3 KB static smem: anchors for the per-h 64x64x32 complex->real contraction
    __shared__ __align__(16) float Pr[NH][64];   // Re(2*Cd * z^a)
    __shared__ __align__(16) float Pi[NH][64];   // Im(2*Cd * z^a)
    __shared__ __align__(16) float Qr[NH][64];   // Re(z^(64b))
    __shared__ __align__(16) float Qi[NH][64];   // Im(z^(64b))
    __shared__ float sdtAr[NH], sdtAi[NH], sCdr[NH], sCdi[NH];

    const int h   = blockIdx.x;
    const int tid = threadIdx.x;

    // ---- phase 1: per-(h,n) scalars, all fp32 (expm1f kills the cancellation)
    if (tid < NH) {
        const int n = tid;
        const float dt  = expf(log_dt[h]);
        const float Arf = -expf(log_A_real[h * NH + n]);
        const float Aif = A_imag[h * NH + n];
        const float xr  = dt * Arf;          // matches reference f32 product
        const float yi  = dt * Aif;

        const float em1 = expm1f(xr);        // e^x - 1, no cancellation
        float sy, cy;
        sincosf(yi, &sy, &cy);
        const float sh   = sinf(0.5f * yi);
        const float numr = em1 * cy - 2.0f * sh * sh;   // e^x cos y - 1
        const float numi = (1.0f + em1) * sy;           // e^x sin y
        const float invd = 1.0f / (Arf * Arf + Aif * Aif);
        const float tr = (numr * Arf + numi * Aif) * invd;   // (e^{dtA}-1)/A
        const float ti = (numi * Arf - numr * Aif) * invd;

        const float Cr = C_real[(h * NH + n) * 2 + 0];
        const float Ci = C_real[(h * NH + n) * 2 + 1];
        sCdr[n] = 2.0f * (Cr * tr - Ci * ti);   // fold the global 2x here
        sCdi[n] = 2.0f * (Cr * ti + Ci * tr);
        sdtAr[n] = xr;
        sdtAi[n] = yi;
    }
    __syncthreads();

    // ---- phase 2: anchors, 16 per thread, fp32 float-float phase reduction ---
    {
        const float INV2PI = 0.15915494309189534f;
        const float PI2_A  = 6.28125f;                    // k*A exact (k < 2^15)
        const float PI2_B  = 1.93500518798828125e-3f;     // 11-bit, k*B exact
        const float PI2_C  = 3.0199159819568e-7f;         // residual
        #pragma unroll
        for (int e = tid; e < NH * 128; e += 256) {
            const int n   = e >> 7;
            const int idx = e & 127;
            const int   l  = (idx < 64) ? idx : ((idx - 64) << 6);
            const float lf = (float)l;

            const float hi = sdtAi[n];
            const float p  = hi * lf;
            const float pe = fmaf(hi, lf, -p);           // exact product residual
            const float k  = rintf(p * INV2PI);
            const float t0 = p - k * PI2_A;              // Sterbenz-exact
            const float t1 = fmaf(-k, PI2_B, t0);
            const float t2 = fmaf(-k, PI2_C, t1);
            const float red = t2 + pe;                   // |red| ~<= pi, ~4e-7 abs

            float sf, cf;
            __sincosf(red, &sf, &cf);
            const float ef = __expf(sdtAr[n] * lf);
            const float wr = ef * cf;
            const float wi = ef * sf;

            if (idx < 64) {
                const float cdr = sCdr[n], cdi = sCdi[n];
                Pr[n][idx] = cdr * wr - cdi * wi;
                Pi[n][idx] = cdr * wi + cdi * wr;
            } else {
                Qr[n][idx - 64] = wr;
                Qi[n][idx - 64] = wi;
            }
        }
    }
    __syncthreads();

    // ---- main loop: 4a x 4b per thread, scalar FFMA (R1-proven) --------------
    const int tx = tid & 15;     // a tile (fast output dim -> coalesced stores)
    const int ty = tid >> 4;     // b tile
    const int a0 = tx * 4;
    const int b0 = ty * 4;

    float acc[4][4];
    #pragma unroll
    for (int j = 0; j < 4; j++)
        #pragma unroll
        for (int i = 0; i < 4; i++) acc[j][i] = 0.0f;

    #pragma unroll 8
    for (int n = 0; n < NH; n++) {
        const float4 pr = *(const float4*)&Pr[n][a0];
        const float4 pi = *(const float4*)&Pi[n][a0];
        const float4 qr = *(const float4*)&Qr[n][b0];
        const float4 qi = *(const float4*)&Qi[n][b0];
        const float prv[4] = {pr.x, pr.y, pr.z, pr.w};
        const float piv[4] = {pi.x, pi.y, pi.z, pi.w};
        const float qrv[4] = {qr.x, qr.y, qr.z, qr.w};
        const float qiv[4] = {qi.x, qi.y, qi.z, qi.w};
        #pragma unroll
        for (int j = 0; j < 4; j++) {
            #pragma unroll
            for (int i = 0; i < 4; i++) {
                acc[j][i] = fmaf(prv[i],  qrv[j], acc[j][i]);
                acc[j][i] = fmaf(-piv[i], qiv[j], acc[j][i]);  // neg folds into FFMA
            }
        }
    }

    // ---- store: K[h][(b0+j)*64 + a0 .. a0+3] ---------------------------------
    float* outh = out + (size_t)h * LLEN;
    #pragma unroll
    for (int j = 0; j < 4; j++) {
        const float4 v = make_float4(acc[j][0], acc[j][1], acc[j][2], acc[j][3]);
        *(float4*)&outh[(b0 + j) * 64 + a0] = v;
    }
}

extern "C" void kernel_launch(void* const* d_in, const int* in_sizes, int n_in,
                              void* d_out, int out_size)
{
    const float* log_dt     = (const float*)d_in[0];
    const float* C_real     = (const float*)d_in[1];
    const float* log_A_real = (const float*)d_in[2];
    const float* A_imag     = (const float*)d_in[3];
    float* out = (float*)d_out;
    s4d_kernel<<<HH, 256>>>(log_dt, C_real, log_A_real, A_imag, out);
}

// round 8
// speedup vs baseline: 2.4063x; 1.5148x over previous
#include <cuda_runtime.h>
#include <cuda_bf16.h>
#include <math.h>
#include <stdint.h>

#define NH    32
#define LLEN  4096
#define BSTRIDE 144   // bytes per b-row in smem B (64 bf16 = 128B + 16B pad -> conflict-free frags)

struct C2 { float r, i; };

static __device__ __forceinline__ C2 cmul(C2 a, C2 b) {
    return { a.r * b.r - a.i * b.i, a.r * b.i + a.i * b.r };
}

// R6-proven fp32 phase reduction: exact Dekker product + 3-term Cody-Waite
static __device__ __forceinline__ float reduce2pi(float yi, float lf) {
    const float INV2PI = 0.15915494309189534f;
    const float PI2_A  = 6.28125f;
    const float PI2_B  = 1.93500518798828125e-3f;
    const float PI2_C  = 3.0199159819568e-7f;
    const float p  = yi * lf;
    const float pe = fmaf(yi, lf, -p);
    const float k  = rintf(p * INV2PI);
    const float t0 = fmaf(-k, PI2_A, p);
    const float t1 = fmaf(-k, PI2_B, t0);
    return fmaf(-k, PI2_C, t1) + pe;
}

static __device__ __forceinline__ C2 zpow(float xr, float yi, float lf) {
    const float red = reduce2pi(yi, lf);
    float sf, cf;
    __sincosf(red, &sf, &cf);
    const float ef = __expf(xr * lf);
    return { ef * cf, ef * sf };
}

// split v0,v1 into bf16 hi pair + lo pair (lower 16 bits = v0)
static __device__ __forceinline__ void split_pack(float v0, float v1,
                                                  uint32_t& hi, uint32_t& lo) {
    __nv_bfloat16 h0 = __float2bfloat16(v0);
    __nv_bfloat16 h1 = __float2bfloat16(v1);
    __nv_bfloat16 l0 = __float2bfloat16(v0 - __bfloat162float(h0));
    __nv_bfloat16 l1 = __float2bfloat16(v1 - __bfloat162float(h1));
    __nv_bfloat162 hp = __halves2bfloat162(h0, h1);
    __nv_bfloat162 lp = __halves2bfloat162(l0, l1);
    hi = *reinterpret_cast<uint32_t*>(&hp);
    lo = *reinterpret_cast<uint32_t*>(&lp);
}

static __device__ __forceinline__ void mma16816(
    float& d0, float& d1, float& d2, float& d3,
    uint32_t a0, uint32_t a1, uint32_t a2, uint32_t a3,
    uint32_t b0, uint32_t b1)
{
    asm volatile(
        "mma.sync.aligned.m16n8k16.row.col.f32.bf16.bf16.f32 "
        "{%0,%1,%2,%3}, {%4,%5,%6,%7}, {%8,%9}, {%0,%1,%2,%3};"
        : "+f"(d0), "+f"(d1), "+f"(d2), "+f"(d3)
        : "r"(a0), "r"(a1), "r"(a2), "r"(a3), "r"(b0), "r"(b1));
}

__global__ __launch_bounds__(128, 4) void s4d_mma_kernel(
    const float* __restrict__ log_dt,
    const float* __restrict__ C_real,
    const float* __restrict__ log_A_real,
    const float* __restrict__ A_imag,
    float* __restrict__ out)
{
    // per-n scalars
    __shared__ float sxr[NH], syi[NH], scdr[NH], scdi[NH];
    __shared__ float sz8r[NH], sz8i[NH], szbr[NH], szbi[NH];   // z^8, z^2048
    // B tiles (hi, lo) as [b][k] bf16 rows of 144B; later overlaid by Dt[64][65] f32
    __shared__ __align__(16) unsigned char sB[2 * 64 * BSTRIDE];   // 18432 B

    const int h   = blockIdx.x;
    const int tid = threadIdx.x;

    // ---- phase 1: per-n scalars (warp 0) -------------------------------------
    if (tid < NH) {
        const int n = tid;
        const float dt  = expf(log_dt[h]);
        const float Arf = -expf(log_A_real[h * NH + n]);
        const float Aif = A_imag[h * NH + n];
        const float xr  = dt * Arf;          // matches reference f32 product
        const float yi  = dt * Aif;

        const float em1 = expm1f(xr);
        float sy, cy;
        sincosf(yi, &sy, &cy);
        const float sh   = sinf(0.5f * yi);
        const float numr = em1 * cy - 2.0f * sh * sh;   // e^x cos y - 1
        const float numi = (1.0f + em1) * sy;           // e^x sin y
        const float invd = 1.0f / (Arf * Arf + Aif * Aif);
        const float tr = (numr * Arf + numi * Aif) * invd;
        const float ti = (numi * Arf - numr * Aif) * invd;
        const float Cr = C_real[(h * NH + n) * 2 + 0];
        const float Ci = C_real[(h * NH + n) * 2 + 1];
        scdr[n] = 2.0f * (Cr * tr - Ci * ti);
        scdi[n] = 2.0f * (Cr * ti + Ci * tr);
        sxr[n] = xr;
        syi[n] = yi;
        C2 z8 = zpow(xr, yi, 8.0f);
        sz8r[n] = z8.r;  sz8i[n] = z8.i;
        C2 zb = zpow(xr, yi, 2048.0f);
        szbr[n] = zb.r;  szbi[n] = zb.i;
    }
    __syncthreads();

    // ---- B producer: Q[b][n] = z^(64b); thread owns (b, b+32) x 8 n ----------
    {
        const int bl = tid & 31;
        const int nb = (tid >> 5) * 8;
        unsigned char* Bh = sB;
        unsigned char* Bl = sB + 64 * BSTRIDE;
        #pragma unroll
        for (int j = 0; j < 8; j++) {
            const int n = nb + j;
            const float xr = sxr[n], yi = syi[n];
            const C2 q  = zpow(xr, yi, (float)(64 * bl));
            const C2 qh = cmul(q, C2{ szbr[n], szbi[n] });   // b + 32
            uint32_t h0, l0, h1, l1;
            split_pack(q.r,  q.i,  h0, l0);
            split_pack(qh.r, qh.i, h1, l1);
            const uint32_t off  = (uint32_t)(bl * BSTRIDE + 4 * n);         // [b][2n]
            const uint32_t off2 = (uint32_t)((bl + 32) * BSTRIDE + 4 * n);
            *(uint32_t*)(Bh + off)  = h0;  *(uint32_t*)(Bl + off)  = l0;
            *(uint32_t*)(Bh + off2) = h1;  *(uint32_t*)(Bl + off2) = l1;
        }
    }

    // ---- A fragments in registers (mma layout), each anchor computed once ----
    const int w = tid >> 5;        // warp -> rows 16w..16w+15
    const int r = (tid >> 2) & 7;  // lane/4
    const int t = tid & 3;         // lane%4
    const float alo = (float)(16 * w + r);

    uint32_t Ah[4][4], Al[4][4];
    #pragma unroll
    for (int kt = 0; kt < 4; kt++) {
        #pragma unroll
        for (int s = 0; s < 2; s++) {
            const int n = 8 * kt + t + 4 * s;
            const float xr = sxr[n], yi = syi[n];
            const C2 cd = { scdr[n], scdi[n] };
            const C2 z8 = { sz8r[n], sz8i[n] };
            const C2 wv = zpow(xr, yi, alo);
            const C2 p  = cmul(cd, wv);        // row a = 16w+r
            const C2 ph = cmul(p, z8);         // row a+8
            split_pack(p.r,  -p.i,  Ah[kt][0 + 2 * s], Al[kt][0 + 2 * s]);  // a0 / a2
            split_pack(ph.r, -ph.i, Ah[kt][1 + 2 * s], Al[kt][1 + 2 * s]);  // a1 / a3
        }
    }
    __syncthreads();

    // ---- MMA mainloop: 8 n-tiles x 4 k-tiles x 3 split passes ----------------
    float d[8][4];
    #pragma unroll
    for (int nt = 0; nt < 8; nt++)
        #pragma unroll
        for (int c = 0; c < 4; c++) d[nt][c] = 0.0f;

    const unsigned char* Bh = sB;
    const unsigned char* Blo = sB + 64 * BSTRIDE;
    #pragma unroll
    for (int nt = 0; nt < 8; nt++) {
        const uint32_t rowoff = (uint32_t)((8 * nt + r) * BSTRIDE + 4 * t);
        #pragma unroll
        for (int kt = 0; kt < 4; kt++) {
            const uint32_t off = rowoff + (uint32_t)(32 * kt);
            const uint32_t bh0 = *(const uint32_t*)(Bh  + off);
            const uint32_t bh1 = *(const uint32_t*)(Bh  + off + 16);
            const uint32_t bl0 = *(const uint32_t*)(Blo + off);
            const uint32_t bl1 = *(const uint32_t*)(Blo + off + 16);
            mma16816(d[nt][0], d[nt][1], d[nt][2], d[nt][3],
                     Ah[kt][0], Ah[kt][1], Ah[kt][2], Ah[kt][3], bh0, bh1);
            mma16816(d[nt][0], d[nt][1], d[nt][2], d[nt][3],
                     Ah[kt][0], Ah[kt][1], Ah[kt][2], Ah[kt][3], bl0, bl1);
            mma16816(d[nt][0], d[nt][1], d[nt][2], d[nt][3],
                     Al[kt][0], Al[kt][1], Al[kt][2], Al[kt][3], bh0, bh1);
        }
    }
    __syncthreads();   // everyone done reading B before Dt overlay

    // ---- stage D[a][b] -> smem Dt[b][a] for coalesced output -----------------
    float (*Dt)[65] = reinterpret_cast<float(*)[65]>(sB);
    {
        const int ar = 16 * w + r;
        #pragma unroll
        for (int nt = 0; nt < 8; nt++) {
            const int bc = 8 * nt + 2 * t;
            Dt[bc    ][ar    ] = d[nt][0];
            Dt[bc + 1][ar    ] = d[nt][1];
            Dt[bc    ][ar + 8] = d[nt][2];
            Dt[bc + 1][ar + 8] = d[nt][3];
        }
    }
    __syncthreads();

    // ---- coalesced store: out[h][b*64+a] -------------------------------------
    float* outh = out + (size_t)h * LLEN;
    #pragma unroll
    for (int i = 0; i < 32; i++) {
        const int gi = i * 128 + tid;
        outh[gi] = Dt[gi >> 6][gi & 63];
    }
}

extern "C" void kernel_launch(void* const* d_in, const int* in_sizes, int n_in,
                              void* d_out, int out_size)
{
    const float* log_dt     = (const float*)d_in[0];
    const float* C_real     = (const float*)d_in[1];
    const float* log_A_real = (const float*)d_in[2];
    const float* A_imag     = (const float*)d_in[3];
    float* out = (float*)d_out;
    s4d_mma_kernel<<<1024, 128>>>(log_dt, C_real, log_A_real, A_imag, out);
}